// round 16
// baseline (speedup 1.0000x reference)
#include <cuda_runtime.h>
#include <cuda_fp16.h>
#include <cstdint>
#include <math.h>

#define BATCH 32
#define TLEN  600
#define CH    64
#define NSEG  50
#define NH    512
#define NPAIR (CH*(CH-1)/2)      // 2016
#define LOGSIG_CH (CH + NPAIR)   // 2080
#define INSZ  (LOGSIG_CH + CH)   // 2144
#define G4    (4*NH)             // 2048
#define MROWS (BATCH*NSEG)       // 1600

#define LBLK  128
#define LTHR  256

// --- HMMA GEMM geometry (proven R14 2-stage config) ---
#define MP   1664
#define KP   2176
#define KHALF 34
#define SROW 80
#define REG_B 10240
#define STG_B (3 * REG_B)
#define SM_HMMA (2 * STG_B)      // 61440

typedef unsigned long long ull;

// ---- scratch (no allocations; zero-init, padded regions never written) ----
// gx layout is S-MAJOR: row m' = s*32 + b
__device__ float g_gx [MROWS * G4];
__device__ float g_gx2[MROWS * G4];
__device__ float g_hP[2][NH * BATCH];
__device__ unsigned int g_flag[NSEG][8];
__device__ unsigned int g_done[13];          // per-mby GEMM completion (target 32)
__device__ __half g_Ah[MP * KP];
__device__ __half g_Al[MP * KP];
__device__ __half g_Bh[(size_t)G4 * KP];

struct SegArgs { int start[NSEG]; int len[NSEG]; };

// ================= helpers =================
__device__ __forceinline__ uint32_t smem_u32(const void* p) {
    uint32_t a;
    asm("{ .reg .u64 t; cvta.to.shared.u64 t, %1; cvt.u32.u64 %0, t; }"
        : "=r"(a) : "l"(p));
    return a;
}
__device__ __forceinline__ void ldsm4(uint32_t* r, uint32_t addr) {
    asm volatile("ldmatrix.sync.aligned.m8n8.x4.shared.b16 {%0,%1,%2,%3}, [%4];"
        : "=r"(r[0]), "=r"(r[1]), "=r"(r[2]), "=r"(r[3]) : "r"(addr));
}
__device__ __forceinline__ void mma_f16(float* d, const uint32_t* a, const uint32_t* b) {
    asm volatile(
        "mma.sync.aligned.m16n8k16.row.col.f32.f16.f16.f32 "
        "{%0,%1,%2,%3}, {%4,%5,%6,%7}, {%8,%9}, {%0,%1,%2,%3};"
        : "+f"(d[0]), "+f"(d[1]), "+f"(d[2]), "+f"(d[3])
        : "r"(a[0]), "r"(a[1]), "r"(a[2]), "r"(a[3]), "r"(b[0]), "r"(b[1]));
}
__device__ __forceinline__ void cpa16(uint32_t dst, const void* src) {
    asm volatile("cp.async.cg.shared.global [%0], [%1], 16;" :: "r"(dst), "l"(src));
}
__device__ __forceinline__ void fma2(ull& d, ull a, ull b) {
    asm("fma.rn.f32x2 %0, %1, %2, %0;" : "+l"(d) : "l"(a), "l"(b));
}
__device__ __forceinline__ float2 unpk(ull v) {
    float2 r;
    asm("mov.b64 {%0, %1}, %2;" : "=f"(r.x), "=f"(r.y) : "l"(v));
    return r;
}
__device__ __forceinline__ ull pack2(float x, float y) {
    ull r;
    asm("mov.b64 %0, {%1, %2};" : "=l"(r) : "f"(x), "f"(y));
    return r;
}
__device__ __forceinline__ void st_splitA(size_t idx, float v) {
    __half h = __float2half_rn(v);
    g_Ah[idx] = h;
    g_Al[idx] = __float2half_rn(v - __half2float(h));
}
__device__ __forceinline__ float fsig(float x) {
    return __fdividef(1.0f, 1.0f + __expf(-x));
}
__device__ __forceinline__ float ftanh(float x) {
    return 1.0f - __fdividef(2.0f, __expf(2.0f * x) + 1.0f);
}
__device__ __forceinline__ unsigned ld_acq(const unsigned int* p) {
    unsigned v;
    asm volatile("ld.acquire.gpu.global.u32 %0, [%1];" : "=r"(v) : "l"(p) : "memory");
    return v;
}

// ============================================================
__global__ void k_reset() {
    int i = threadIdx.x;
    if (i < NSEG * 8) ((unsigned int*)g_flag)[i] = 0u;
    if (i < 13) g_done[i] = 0u;
}

// ============================================================
// Kernel 1: log-signature features -> split fp16 A operand
//   A row index is S-MAJOR: m' = s*32 + b
// ============================================================
__global__ void k_feats(const float* __restrict__ x, SegArgs seg) {
    int bs = blockIdx.x;
    int b = bs / NSEG, s = bs % NSEG;
    int st = seg.start[s], len = seg.len[s];

    __shared__ float xs[17][CH];
    const float* xp = x + ((size_t)b * TLEN + st) * CH;
    for (int idx = threadIdx.x; idx < (len + 1) * CH; idx += blockDim.x)
        xs[idx >> 6][idx & 63] = xp[idx];
    __syncthreads();

    size_t base = (size_t)(s * BATCH + b) * KP;

    if (threadIdx.x < CH) {
        int c = threadIdx.x;
        float xa = xs[0][c], xe = xs[len][c];
        st_splitA(base + c, xe - xa);
        st_splitA(base + LOGSIG_CH + c, xa);
    }

    for (int p = threadIdx.x; p < NPAIR; p += blockDim.x) {
        int i = (int)(63.5f - sqrtf(fmaxf(63.5f * 63.5f - 2.0f * (float)p, 0.0f)));
        if (i < 0) i = 0;
        while (i > 0 && p < i * (127 - i) / 2) i--;
        while (p >= (i + 1) * (126 - i) / 2) i++;
        int j = i + 1 + (p - i * (127 - i) / 2);

        float acc = 0.0f;
        for (int t = 0; t < len; t++)
            acc += xs[t][i] * xs[t + 1][j] - xs[t][j] * xs[t + 1][i];

        float xai = xs[0][i], xaj = xs[0][j];
        float inci = xs[len][i] - xai;
        float incj = xs[len][j] - xaj;
        st_splitA(base + CH + p, 0.5f * (acc - xai * incj + xaj * inci));
    }
}

// ============================================================
// Pack B: w_ih fp32 -> fp16 (hi only), row-major padded
// ============================================================
__global__ void k_packB(const float* __restrict__ w_ih) {  // grid (34, 16)
    int kc = blockIdx.x, nt = blockIdx.y;
    for (int u = threadIdx.x; u < 1024; u += 128) {
        int r = u >> 3, cu = u & 7;
        int n = nt * 128 + r, k = kc * 64 + cu * 8;
        float v[8] = {0,0,0,0,0,0,0,0};
        if (k < INSZ) {
            const float* src = w_ih + (size_t)n * INSZ + k;
            float4 a = *(const float4*)src, b2 = *(const float4*)(src + 4);
            v[0]=a.x; v[1]=a.y; v[2]=a.z; v[3]=a.w;
            v[4]=b2.x; v[5]=b2.y; v[6]=b2.z; v[7]=b2.w;
        }
        __half h[8];
        #pragma unroll
        for (int i = 0; i < 8; i++) h[i] = __float2half_rn(v[i]);
        *(uint4*)(g_Bh + (size_t)n * KP + k) = *(uint4*)h;
    }
}

// ============================================================
// Kernel 2: HMMA GEMM, fp16 2-term, split-K 2-way, 2-stage.
//   NEW: per-mby completion counter in epilogue.
// ============================================================
__global__ __launch_bounds__(256, 2)
void k_hmma(const float* __restrict__ b_ih, const float* __restrict__ b_hh) {
    extern __shared__ __align__(128) char smem[];
    uint32_t sb = smem_u32(smem);

    int tid = threadIdx.x;
    int warp = tid >> 5, lane = tid & 31;
    int nbx = blockIdx.x, mby = blockIdx.y;
    int kz0 = blockIdx.z * KHALF;
    int wm = (warp & 3) * 32;
    int wn = (warp >> 2) * 64;

    float acc[2][8][4];
    #pragma unroll
    for (int i = 0; i < 2; i++)
        #pragma unroll
        for (int j = 0; j < 8; j++)
            #pragma unroll
            for (int k = 0; k < 4; k++) acc[i][j][k] = 0.0f;

    auto issue = [&](int stg, int kc) {
        uint32_t dstb = sb + stg * STG_B;
        #pragma unroll
        for (int i = 0; i < 6; i++) {
            const int region = i >> 1;
            int rem = tid + (i & 1) * 256;
            int r = rem >> 2, q = rem & 3;
            const __half* base =
                (region == 0) ? g_Ah : (region == 1) ? g_Al : g_Bh;
            size_t row = (region < 2) ? (size_t)(mby * 128 + r)
                                      : (size_t)(nbx * 128 + r);
            cpa16(dstb + region * REG_B + r * SROW + q * 16,
                  base + row * KP + kc * 32 + q * 8);
        }
        asm volatile("cp.async.commit_group;");
    };

    issue(0, kz0);

    uint32_t a_row = lane & 15;
    uint32_t a_colq = (lane >> 4) * 8;
    uint32_t b_n = ((lane >> 4) & 1) * 8 + (lane & 7);
    uint32_t b_kq = ((lane >> 3) & 1) * 8;

    for (int kcl = 0; kcl < KHALF; kcl++) {
        int s = kcl & 1;
        asm volatile("cp.async.wait_group 0;" ::: "memory");
        __syncthreads();
        if (kcl + 1 < KHALF) issue(s ^ 1, kz0 + kcl + 1);

        uint32_t stb = sb + s * STG_B;
        #pragma unroll
        for (int k16 = 0; k16 < 32; k16 += 16) {
            uint32_t ah[2][4], al[2][4], bb[8][2];
            #pragma unroll
            for (int mt = 0; mt < 2; mt++) {
                uint32_t ad = stb + (wm + mt * 16 + a_row) * SROW
                            + (a_colq + k16) * 2;
                ldsm4(ah[mt], ad);
                ldsm4(al[mt], ad + REG_B);
            }
            uint32_t bkoff = (k16 + b_kq) * 2;
            #pragma unroll
            for (int np = 0; np < 4; np++) {
                uint32_t bd = stb + 2 * REG_B
                            + (wn + np * 16 + b_n) * SROW + bkoff;
                ldsm4(&bb[np * 2][0], bd);
            }
            #pragma unroll
            for (int mt = 0; mt < 2; mt++)
                #pragma unroll
                for (int nt = 0; nt < 8; nt++) {
                    mma_f16(acc[mt][nt], ah[mt], bb[nt]);
                    mma_f16(acc[mt][nt], al[mt], bb[nt]);
                }
        }
        __syncthreads();
    }

    float* dst = (blockIdx.z == 0) ? g_gx : g_gx2;
    int tr = lane >> 2;
    int tc = (lane & 3) * 2;
    #pragma unroll
    for (int mt = 0; mt < 2; mt++) {
        #pragma unroll
        for (int nt = 0; nt < 8; nt++) {
            int col = nbx * 128 + wn + nt * 8 + tc;
            float bs0 = 0.0f, bs1 = 0.0f;
            if (blockIdx.z == 0) {
                bs0 = b_ih[col] + b_hh[col];
                bs1 = b_ih[col + 1] + b_hh[col + 1];
            }
            int m0 = mby * 128 + wm + mt * 16 + tr;
            float* d = acc[mt][nt];
            if (m0 < MROWS) {
                float2 v = {d[0] + bs0, d[1] + bs1};
                *(float2*)(dst + (size_t)m0 * G4 + col) = v;
            }
            if (m0 + 8 < MROWS) {
                float2 v = {d[2] + bs0, d[3] + bs1};
                *(float2*)(dst + (size_t)(m0 + 8) * G4 + col) = v;
            }
        }
    }

    // publish tile completion (32 CTAs per mby: 16 nbx x 2 kz)
    __threadfence();
    __syncthreads();
    if (tid == 0) {
        asm volatile("red.release.gpu.global.add.u32 [%0], 1;"
                     :: "l"(&g_done[mby]) : "memory");
    }
}

// ============================================================
// Kernel 3: PERSISTENT LSTM (<=128 regs for co-residency).
//   gx is s-major; waits on g_done[s>>2] before consuming.
//   h matvec staged in two 16-reg halves.
// ============================================================
__global__ __launch_bounds__(LTHR, 2)
void k_lstm_persist(const float* __restrict__ whh,
                    float* __restrict__ out) {
    __shared__ float ws[16 * NH];
    __shared__ float ps[8 * 16 * 32];

    int tid  = threadIdx.x;
    int warp = tid >> 5;
    int lane = tid & 31;
    int n0 = blockIdx.x * 4;
    int kw = warp * 64;
    int mychunk = blockIdx.x >> 4;

    for (int i = tid; i < 16 * (NH / 4); i += LTHR) {
        int r = i >> 7, kq = i & 127;
        int g = r >> 2, u = r & 3;
        ((float4*)ws)[r * (NH / 4) + kq] =
            ((const float4*)(whh + ((size_t)g * NH + n0 + u) * NH))[kq];
    }
    __syncthreads();

    float cc = 0.0f;
    int ub_u = tid >> 5;
    int ub_b = tid & 31;
    int hidx = ((n0 + ub_u) >> 1) * 64 + ub_b * 2 + ((n0 + ub_u) & 1);

    float pgx[4];
    if (tid < 128) {
        // wait for gx tile covering step 0
        while (ld_acq(&g_done[0]) < 32u) __nanosleep(256);
        size_t row = (size_t)ub_b;           // s=0 -> row = b
        #pragma unroll
        for (int g = 0; g < 4; g++) {
            size_t idx = row * G4 + g * NH + n0 + ub_u;
            pgx[g] = g_gx[idx] + g_gx2[idx];
        }
    }

    for (int s = 0; s < NSEG; s++) {
        if (s > 0) {
            const unsigned int* fp = &g_flag[s - 1][warp];
            while (ld_acq(fp) < 16u) { }

            const float2* src = (const float2*)g_hP[(s - 1) & 1]
                              + (kw >> 1) * 32 + lane;
            ull acc2[16];
            #pragma unroll
            for (int r = 0; r < 16; r++) acc2[r] = 0ull;

            // two 16-reg halves to stay under 128 regs
            #pragma unroll
            for (int half = 0; half < 2; half++) {
                ull hreg[16];
                #pragma unroll
                for (int i = 0; i < 16; i++) {
                    float2 hv = __ldcg(src + (half * 16 + i) * 32);
                    hreg[i] = pack2(hv.x, hv.y);
                }
                int kb = kw + half * 32;
                #pragma unroll
                for (int kk4 = 0; kk4 < 8; kk4++) {
                    ull h0 = hreg[2 * kk4], h1 = hreg[2 * kk4 + 1];
                    #pragma unroll
                    for (int r = 0; r < 16; r++) {
                        ulonglong2 wv =
                            *(const ulonglong2*)&ws[r * NH + kb + kk4 * 4];
                        fma2(acc2[r], wv.x, h0);
                        fma2(acc2[r], wv.y, h1);
                    }
                }
            }
            #pragma unroll
            for (int r = 0; r < 16; r++) {
                float2 v2 = unpk(acc2[r]);
                ps[(warp * 16 + r) * 32 + lane] = v2.x + v2.y;
            }
        }
        __syncthreads();

        if (tid < 128) {
            int b = ub_b, u = ub_u;
            float gsum[4];
            #pragma unroll
            for (int g = 0; g < 4; g++) {
                float a = pgx[g];
                if (s > 0) {
                    int row = g * 4 + u;
                    #pragma unroll
                    for (int w = 0; w < 8; w++)
                        a += ps[(w * 16 + row) * 32 + b];
                }
                gsum[g] = a;
            }
            float gi = fsig(gsum[0]);
            float gf = fsig(gsum[1]);
            float gg = ftanh(gsum[2]);
            float go = fsig(gsum[3]);

            float cn = gf * cc + gi * gg;
            float hn = go * ftanh(cn);
            cc = cn;

            g_hP[s & 1][hidx] = hn;
            out[((size_t)b * NSEG + s) * NH + n0 + u] = hn;

            if (s < NSEG - 1) {
                asm volatile("bar.sync 7, 128;" ::: "memory");
                if (tid == 0) {
                    asm volatile("red.release.gpu.global.add.u32 [%0], 1;"
                                 :: "l"(&g_flag[s][mychunk]) : "memory");
                }
            }
        }
        __syncthreads();

        if (s < NSEG - 1) {
            if (tid < 128) {
                int sn = s + 1;
                // gate on GEMM tile for step sn (overlap phase only)
                const unsigned int* dp = &g_done[sn >> 2];
                while (ld_acq(dp) < 32u) __nanosleep(256);
                size_t row = (size_t)(sn * BATCH + ub_b);
                #pragma unroll
                for (int g = 0; g < 4; g++) {
                    size_t idx = row * G4 + g * NH + n0 + ub_u;
                    pgx[g] = g_gx[idx] + g_gx2[idx];
                }
            }
        }
    }
}

// ============================================================
extern "C" void kernel_launch(void* const* d_in, const int* in_sizes, int n_in,
                              void* d_out, int out_size) {
    const float* x    = (const float*)d_in[0];
    const float* w_ih = (const float*)d_in[1];
    const float* w_hh = (const float*)d_in[2];
    const float* b_ih = (const float*)d_in[3];
    const float* b_hh = (const float*)d_in[4];
    float* out = (float*)d_out;

    SegArgs seg;
    const double step = 599.0 / 50.0;
    int tv[NSEG + 1];
    for (int i = 0; i <= NSEG; i++)
        tv[i] = (int)nearbyint(1.0 + step * (double)i);
    tv[NSEG] = TLEN;
    for (int s = 0; s < NSEG; s++) {
        seg.start[s] = tv[s] - 1;
        int len = tv[s + 1] - tv[s];
        if (len > 16) len = 16;
        seg.len[s] = len;
    }

    cudaFuncSetAttribute(k_hmma, cudaFuncAttributeMaxDynamicSharedMemorySize, SM_HMMA);

    // fork: LSTM runs concurrently with the GEMM, gated by g_done flags.
    cudaStream_t s1;
    cudaStreamCreate(&s1);
    cudaEvent_t e1, e2;
    cudaEventCreateWithFlags(&e1, cudaEventDisableTiming);
    cudaEventCreateWithFlags(&e2, cudaEventDisableTiming);

    k_reset<<<1, 512>>>();
    k_feats<<<MROWS, 256>>>(x, seg);
    k_packB<<<dim3(34, 16), 128>>>(w_ih);

    cudaEventRecord(e1, 0);
    cudaStreamWaitEvent(s1, e1, 0);

    k_hmma<<<dim3(16, 13, 2), 256, SM_HMMA>>>(b_ih, b_hh);
    k_lstm_persist<<<LBLK, LTHR, 0, s1>>>(w_hh, out);

    cudaEventRecord(e2, s1);
    cudaStreamWaitEvent(0, e2, 0);

    cudaEventDestroy(e1);
    cudaEventDestroy(e2);
    cudaStreamDestroy(s1);
}

// round 17
// speedup vs baseline: 1.4986x; 1.4986x over previous
#include <cuda_runtime.h>
#include <cuda_fp16.h>
#include <cstdint>
#include <math.h>

#define BATCH 32
#define TLEN  600
#define CH    64
#define NSEG  50
#define NH    512
#define NPAIR (CH*(CH-1)/2)      // 2016
#define LOGSIG_CH (CH + NPAIR)   // 2080
#define INSZ  (LOGSIG_CH + CH)   // 2144
#define G4    (4*NH)             // 2048
#define MROWS (BATCH*NSEG)       // 1600

#define LBLK  128
#define LTHR  256

// --- HMMA GEMM geometry (R14 proven config) ---
#define MP   1664
#define KP   2176
#define KHALF 34
#define SROW 80
#define REG_B 10240
#define STG_B (3 * REG_B)
#define SM_HMMA (2 * STG_B)

// LSTM w smem row stride in halfs (512 + 8 pad -> 1040B rows)
#define WSTR 520

typedef unsigned long long ull;

// ---- scratch (no allocations; zero-init, padded never written) ----
__device__ float g_gx [MROWS * G4];
__device__ float g_gx2[MROWS * G4];
__device__ ull   g_hQ[2][(NH / 2) * BATCH];   // (hh2, hl2) per (kpair, b)
__device__ unsigned int g_flag[NSEG][8];
__device__ __half g_Ah[MP * KP];
__device__ __half g_Al[MP * KP];
__device__ __half g_Bh[(size_t)G4 * KP];

struct SegArgs { int start[NSEG]; int len[NSEG]; };

// ================= helpers =================
__device__ __forceinline__ uint32_t smem_u32(const void* p) {
    uint32_t a;
    asm("{ .reg .u64 t; cvta.to.shared.u64 t, %1; cvt.u32.u64 %0, t; }"
        : "=r"(a) : "l"(p));
    return a;
}
__device__ __forceinline__ void ldsm4(uint32_t* r, uint32_t addr) {
    asm volatile("ldmatrix.sync.aligned.m8n8.x4.shared.b16 {%0,%1,%2,%3}, [%4];"
        : "=r"(r[0]), "=r"(r[1]), "=r"(r[2]), "=r"(r[3]) : "r"(addr));
}
__device__ __forceinline__ void mma_f16(float* d, const uint32_t* a, const uint32_t* b) {
    asm volatile(
        "mma.sync.aligned.m16n8k16.row.col.f32.f16.f16.f32 "
        "{%0,%1,%2,%3}, {%4,%5,%6,%7}, {%8,%9}, {%0,%1,%2,%3};"
        : "+f"(d[0]), "+f"(d[1]), "+f"(d[2]), "+f"(d[3])
        : "r"(a[0]), "r"(a[1]), "r"(a[2]), "r"(a[3]), "r"(b[0]), "r"(b[1]));
}
__device__ __forceinline__ void cpa16(uint32_t dst, const void* src) {
    asm volatile("cp.async.cg.shared.global [%0], [%1], 16;" :: "r"(dst), "l"(src));
}
__device__ __forceinline__ void st_splitA(size_t idx, float v) {
    __half h = __float2half_rn(v);
    g_Ah[idx] = h;
    g_Al[idx] = __float2half_rn(v - __half2float(h));
}
__device__ __forceinline__ float fsig(float x) {
    return __fdividef(1.0f, 1.0f + __expf(-x));
}
__device__ __forceinline__ float ftanh(float x) {
    return 1.0f - __fdividef(2.0f, __expf(2.0f * x) + 1.0f);
}
__device__ __forceinline__ unsigned ld_acq(const unsigned int* p) {
    unsigned v;
    asm volatile("ld.acquire.gpu.global.u32 %0, [%1];" : "=r"(v) : "l"(p) : "memory");
    return v;
}

// ============================================================
__global__ void k_reset() {
    int i = threadIdx.x;
    if (i < NSEG * 8) ((unsigned int*)g_flag)[i] = 0u;
}

// ============================================================
// Kernel 1: log-signature features -> split fp16 A (b-major)
// ============================================================
__global__ void k_feats(const float* __restrict__ x, SegArgs seg) {
    int bs = blockIdx.x;
    int b = bs / NSEG, s = bs % NSEG;
    int st = seg.start[s], len = seg.len[s];

    __shared__ float xs[17][CH];
    const float* xp = x + ((size_t)b * TLEN + st) * CH;
    for (int idx = threadIdx.x; idx < (len + 1) * CH; idx += blockDim.x)
        xs[idx >> 6][idx & 63] = xp[idx];
    __syncthreads();

    size_t base = (size_t)bs * KP;

    if (threadIdx.x < CH) {
        int c = threadIdx.x;
        float xa = xs[0][c], xe = xs[len][c];
        st_splitA(base + c, xe - xa);
        st_splitA(base + LOGSIG_CH + c, xa);
    }

    for (int p = threadIdx.x; p < NPAIR; p += blockDim.x) {
        int i = (int)(63.5f - sqrtf(fmaxf(63.5f * 63.5f - 2.0f * (float)p, 0.0f)));
        if (i < 0) i = 0;
        while (i > 0 && p < i * (127 - i) / 2) i--;
        while (p >= (i + 1) * (126 - i) / 2) i++;
        int j = i + 1 + (p - i * (127 - i) / 2);

        float acc = 0.0f;
        for (int t = 0; t < len; t++)
            acc += xs[t][i] * xs[t + 1][j] - xs[t][j] * xs[t + 1][i];

        float xai = xs[0][i], xaj = xs[0][j];
        float inci = xs[len][i] - xai;
        float incj = xs[len][j] - xaj;
        st_splitA(base + CH + p, 0.5f * (acc - xai * incj + xaj * inci));
    }
}

// ============================================================
// Pack B: w_ih fp32 -> fp16 (hi only)
// ============================================================
__global__ void k_packB(const float* __restrict__ w_ih) {  // grid (34, 16)
    int kc = blockIdx.x, nt = blockIdx.y;
    for (int u = threadIdx.x; u < 1024; u += 128) {
        int r = u >> 3, cu = u & 7;
        int n = nt * 128 + r, k = kc * 64 + cu * 8;
        float v[8] = {0,0,0,0,0,0,0,0};
        if (k < INSZ) {
            const float* src = w_ih + (size_t)n * INSZ + k;
            float4 a = *(const float4*)src, b2 = *(const float4*)(src + 4);
            v[0]=a.x; v[1]=a.y; v[2]=a.z; v[3]=a.w;
            v[4]=b2.x; v[5]=b2.y; v[6]=b2.z; v[7]=b2.w;
        }
        __half h[8];
        #pragma unroll
        for (int i = 0; i < 8; i++) h[i] = __float2half_rn(v[i]);
        *(uint4*)(g_Bh + (size_t)n * KP + k) = *(uint4*)h;
    }
}

// ============================================================
// Kernel 2: HMMA GEMM (exact R14)
// ============================================================
__global__ __launch_bounds__(256, 2)
void k_hmma(const float* __restrict__ b_ih, const float* __restrict__ b_hh) {
    extern __shared__ __align__(128) char smem[];
    uint32_t sb = smem_u32(smem);

    int tid = threadIdx.x;
    int warp = tid >> 5, lane = tid & 31;
    int nbx = blockIdx.x, mby = blockIdx.y;
    int kz0 = blockIdx.z * KHALF;
    int wm = (warp & 3) * 32;
    int wn = (warp >> 2) * 64;

    float acc[2][8][4];
    #pragma unroll
    for (int i = 0; i < 2; i++)
        #pragma unroll
        for (int j = 0; j < 8; j++)
            #pragma unroll
            for (int k = 0; k < 4; k++) acc[i][j][k] = 0.0f;

    auto issue = [&](int stg, int kc) {
        uint32_t dstb = sb + stg * STG_B;
        #pragma unroll
        for (int i = 0; i < 6; i++) {
            const int region = i >> 1;
            int rem = tid + (i & 1) * 256;
            int r = rem >> 2, q = rem & 3;
            const __half* base =
                (region == 0) ? g_Ah : (region == 1) ? g_Al : g_Bh;
            size_t row = (region < 2) ? (size_t)(mby * 128 + r)
                                      : (size_t)(nbx * 128 + r);
            cpa16(dstb + region * REG_B + r * SROW + q * 16,
                  base + row * KP + kc * 32 + q * 8);
        }
        asm volatile("cp.async.commit_group;");
    };

    issue(0, kz0);

    uint32_t a_row = lane & 15;
    uint32_t a_colq = (lane >> 4) * 8;
    uint32_t b_n = ((lane >> 4) & 1) * 8 + (lane & 7);
    uint32_t b_kq = ((lane >> 3) & 1) * 8;

    for (int kcl = 0; kcl < KHALF; kcl++) {
        int s = kcl & 1;
        asm volatile("cp.async.wait_group 0;" ::: "memory");
        __syncthreads();
        if (kcl + 1 < KHALF) issue(s ^ 1, kz0 + kcl + 1);

        uint32_t stb = sb + s * STG_B;
        #pragma unroll
        for (int k16 = 0; k16 < 32; k16 += 16) {
            uint32_t ah[2][4], al[2][4], bb[8][2];
            #pragma unroll
            for (int mt = 0; mt < 2; mt++) {
                uint32_t ad = stb + (wm + mt * 16 + a_row) * SROW
                            + (a_colq + k16) * 2;
                ldsm4(ah[mt], ad);
                ldsm4(al[mt], ad + REG_B);
            }
            uint32_t bkoff = (k16 + b_kq) * 2;
            #pragma unroll
            for (int np = 0; np < 4; np++) {
                uint32_t bd = stb + 2 * REG_B
                            + (wn + np * 16 + b_n) * SROW + bkoff;
                ldsm4(&bb[np * 2][0], bd);
            }
            #pragma unroll
            for (int mt = 0; mt < 2; mt++)
                #pragma unroll
                for (int nt = 0; nt < 8; nt++) {
                    mma_f16(acc[mt][nt], ah[mt], bb[nt]);
                    mma_f16(acc[mt][nt], al[mt], bb[nt]);
                }
        }
        __syncthreads();
    }

    float* dst = (blockIdx.z == 0) ? g_gx : g_gx2;
    int tr = lane >> 2;
    int tc = (lane & 3) * 2;
    #pragma unroll
    for (int mt = 0; mt < 2; mt++) {
        #pragma unroll
        for (int nt = 0; nt < 8; nt++) {
            int col = nbx * 128 + wn + nt * 8 + tc;
            float bs0 = 0.0f, bs1 = 0.0f;
            if (blockIdx.z == 0) {
                bs0 = b_ih[col] + b_hh[col];
                bs1 = b_ih[col + 1] + b_hh[col + 1];
            }
            int m0 = mby * 128 + wm + mt * 16 + tr;
            float* d = acc[mt][nt];
            if (m0 < MROWS) {
                float2 v = {d[0] + bs0, d[1] + bs1};
                *(float2*)(dst + (size_t)m0 * G4 + col) = v;
            }
            if (m0 + 8 < MROWS) {
                float2 v = {d[2] + bs0, d[3] + bs1};
                *(float2*)(dst + (size_t)(m0 + 8) * G4 + col) = v;
            }
        }
    }
}

// ============================================================
// Kernel 3: PERSISTENT LSTM with tensor-core matvec.
//   Block = 4 hidden units (16 gate-rows). w_hh split hi/lo
//   fp16 in smem; per-warp A fragments (m16k64) preloaded in
//   registers via ldmatrix. h exchanged as (hh2,hl2) 8B quads.
//   Per step per warp: 32 LDG.64 + 48 HMMA. 3-term product.
// ============================================================
__global__ __launch_bounds__(LTHR, 1)
void k_lstm_persist(const float* __restrict__ whh,
                    float* __restrict__ out) {
    __shared__ __half wsh[16 * WSTR];       // 16.6 KB
    __shared__ __half wsl[16 * WSTR];       // 16.6 KB
    __shared__ float ps[8 * 16 * 33];       // 16.9 KB

    int tid  = threadIdx.x;
    int warp = tid >> 5;
    int lane = tid & 31;
    int n0 = blockIdx.x * 4;
    int kw = warp * 64;
    int mychunk = blockIdx.x >> 4;

    // load + split w_hh rows (g*4+u) -> fp16 hi/lo
    for (int i = tid; i < 16 * NH; i += LTHR) {
        int r = i >> 9, k = i & 511;
        int g = r >> 2, u = r & 3;
        float w = whh[((size_t)g * NH + n0 + u) * NH + k];
        __half hh = __float2half_rn(w);
        wsh[r * WSTR + k] = hh;
        wsl[r * WSTR + k] = __float2half_rn(w - __half2float(hh));
    }
    __syncthreads();

    // preload A fragments: m16 x k16 chunks c=0..3 at k = kw + c*16
    uint32_t afh[4][4], afl[4][4];
    {
        uint32_t wsh_b = smem_u32(wsh), wsl_b = smem_u32(wsl);
        uint32_t a_row = lane & 15;
        uint32_t a_colq = (lane >> 4) * 8;
        #pragma unroll
        for (int c = 0; c < 4; c++) {
            uint32_t off = a_row * (WSTR * 2) + (kw + c * 16 + a_colq) * 2;
            ldsm4(afh[c], wsh_b + off);
            ldsm4(afl[c], wsl_b + off);
        }
    }

    float cc = 0.0f;
    int ub_u = tid >> 5;
    int ub_b = tid & 31;

    float pgx[4];
    if (tid < 128) {
        size_t off = (size_t)ub_b * NSEG * G4;
        #pragma unroll
        for (int g = 0; g < 4; g++) {
            size_t idx = off + g * NH + n0 + ub_u;
            pgx[g] = g_gx[idx] + g_gx2[idx];
        }
    }

    int l4 = lane & 3;        // k-pair sub-index
    int l8 = lane >> 2;       // batch sub-index
    int kwp = kw >> 1;        // base k-pair of this warp's window

    for (int s = 0; s < NSEG; s++) {
        if (s > 0) {
            const unsigned int* fp = &g_flag[s - 1][warp];
            while (ld_acq(fp) < 16u) { }

            const ull* hq = g_hQ[(s - 1) & 1];
            // load all 32 quads up-front: q[c][t][0]=kpair, [1]=kpair+4
            ull q[4][4][2];
            #pragma unroll
            for (int c = 0; c < 4; c++) {
                int kp = kwp + c * 8 + l4;
                #pragma unroll
                for (int t = 0; t < 4; t++) {
                    int b = t * 8 + l8;
                    q[c][t][0] = __ldcg(hq + kp * 32 + b);
                    q[c][t][1] = __ldcg(hq + (kp + 4) * 32 + b);
                }
            }

            float d[4][4];
            #pragma unroll
            for (int t = 0; t < 4; t++)
                #pragma unroll
                for (int i = 0; i < 4; i++) d[t][i] = 0.0f;

            #pragma unroll
            for (int c = 0; c < 4; c++) {
                #pragma unroll
                for (int t = 0; t < 4; t++) {
                    uint32_t bh[2], bl[2];
                    bh[0] = (uint32_t)(q[c][t][0] & 0xffffffffull);
                    bl[0] = (uint32_t)(q[c][t][0] >> 32);
                    bh[1] = (uint32_t)(q[c][t][1] & 0xffffffffull);
                    bl[1] = (uint32_t)(q[c][t][1] >> 32);
                    mma_f16(d[t], afh[c], bh);
                    mma_f16(d[t], afl[c], bh);
                    mma_f16(d[t], afh[c], bl);
                }
            }
            // scatter D -> ps: lane holds rows l8, l8+8; cols (l4*2, +1)
            #pragma unroll
            for (int t = 0; t < 4; t++) {
                int bcol = t * 8 + l4 * 2;
                ps[(warp * 16 + l8) * 33 + bcol]     = d[t][0];
                ps[(warp * 16 + l8) * 33 + bcol + 1] = d[t][1];
                ps[(warp * 16 + l8 + 8) * 33 + bcol]     = d[t][2];
                ps[(warp * 16 + l8 + 8) * 33 + bcol + 1] = d[t][3];
            }
        }
        __syncthreads();

        if (tid < 128) {
            int b = ub_b, u = ub_u;
            float gsum[4];
            #pragma unroll
            for (int g = 0; g < 4; g++) {
                float a = pgx[g];
                if (s > 0) {
                    int row = g * 4 + u;
                    #pragma unroll
                    for (int w = 0; w < 8; w++)
                        a += ps[(w * 16 + row) * 33 + b];
                }
                gsum[g] = a;
            }
            float gi = fsig(gsum[0]);
            float gf = fsig(gsum[1]);
            float gg = ftanh(gsum[2]);
            float go = fsig(gsum[3]);

            float cn = gf * cc + gi * gg;
            float hn = go * ftanh(cn);
            cc = cn;

            // store h as (hh, hl) fp16 into the 8B quad
            {
                int n = n0 + u;
                __half hh = __float2half_rn(hn);
                __half hl = __float2half_rn(hn - __half2float(hh));
                __half* base = (__half*)(g_hQ[s & 1] + ((n >> 1) * 32 + b));
                base[n & 1] = hh;
                base[2 + (n & 1)] = hl;
            }
            out[((size_t)b * NSEG + s) * NH + n0 + u] = hn;

            if (s < NSEG - 1) {
                asm volatile("bar.sync 7, 128;" ::: "memory");
                if (tid == 0) {
                    asm volatile("red.release.gpu.global.add.u32 [%0], 1;"
                                 :: "l"(&g_flag[s][mychunk]) : "memory");
                }
            }
        }
        __syncthreads();

        if (s < NSEG - 1) {
            if (tid < 128) {
                size_t off = ((size_t)ub_b * NSEG + s + 1) * G4;
                #pragma unroll
                for (int g = 0; g < 4; g++) {
                    size_t idx = off + g * NH + n0 + ub_u;
                    pgx[g] = g_gx[idx] + g_gx2[idx];
                }
            }
        }
    }
}

// ============================================================
extern "C" void kernel_launch(void* const* d_in, const int* in_sizes, int n_in,
                              void* d_out, int out_size) {
    const float* x    = (const float*)d_in[0];
    const float* w_ih = (const float*)d_in[1];
    const float* w_hh = (const float*)d_in[2];
    const float* b_ih = (const float*)d_in[3];
    const float* b_hh = (const float*)d_in[4];
    float* out = (float*)d_out;

    SegArgs seg;
    const double step = 599.0 / 50.0;
    int tv[NSEG + 1];
    for (int i = 0; i <= NSEG; i++)
        tv[i] = (int)nearbyint(1.0 + step * (double)i);
    tv[NSEG] = TLEN;
    for (int s = 0; s < NSEG; s++) {
        seg.start[s] = tv[s] - 1;
        int len = tv[s + 1] - tv[s];
        if (len > 16) len = 16;
        seg.len[s] = len;
    }

    cudaFuncSetAttribute(k_hmma, cudaFuncAttributeMaxDynamicSharedMemorySize, SM_HMMA);

    k_reset<<<1, 512>>>();
    k_feats<<<MROWS, 256>>>(x, seg);
    k_packB<<<dim3(34, 16), 128>>>(w_ih);
    k_hmma<<<dim3(16, 13, 2), 256, SM_HMMA>>>(b_ih, b_hh);
    k_lstm_persist<<<LBLK, LTHR>>>(w_hh, out);
}